// round 10
// baseline (speedup 1.0000x reference)
#include <cuda_runtime.h>
#include <cstdint>

// Problem constants
#define NPTS   131072
#define DIMK   64
#define KCENT  1024
#define INROW  128

#define THREADS 256          // 8 warps; each warp owns 16 points
#define BM      128          // points per CTA
#define NTILES  (KCENT / 8)  // 128 n8-tiles
#define TPC     8            // tiles per chunk (64 centers)
#define NCHUNK  (NTILES / TPC)           // 16
#define CHUNK_BYTES (TPC * 8 * 32 * 16)  // 32768
#define CN_OFF  (2 * CHUNK_BYTES)        // after the two chunk buffers
#define SMEM_REQ (CN_OFF + KCENT * 4)    // 69632

__device__ float g_cnorm[KCENT];
// B fragments, tile-major: [tile(128)][kstep(8)][lane(32)] x uint4
// uint4 = (h0, h1, l0, l1): tf32 hi/lo of centers[n][k], centers[n][k+4],
// n = tile*8 + lane/4, k = kstep*8 + lane%4.
__device__ __align__(16) uint4 g_bfrag[NTILES * 8 * 32];

// ---------------- helpers ----------------
__device__ __forceinline__ unsigned to_tf32(float x) {
    unsigned u;
    asm("cvt.rna.tf32.f32 %0, %1;" : "=r"(u) : "f"(x));
    return u;
}
__device__ __forceinline__ void split_tf32(float x, unsigned& hi, unsigned& lo) {
    hi = to_tf32(x);
    lo = to_tf32(x - __uint_as_float(hi));
}
__device__ __forceinline__ void mma_tf32(float d[4], const unsigned a[4],
                                         unsigned b0, unsigned b1) {
    asm("mma.sync.aligned.m16n8k8.row.col.f32.tf32.tf32.f32 "
        "{%0,%1,%2,%3}, {%4,%5,%6,%7}, {%8,%9}, {%0,%1,%2,%3};"
        : "+f"(d[0]), "+f"(d[1]), "+f"(d[2]), "+f"(d[3])
        : "r"(a[0]), "r"(a[1]), "r"(a[2]), "r"(a[3]), "r"(b0), "r"(b1));
}
__device__ __forceinline__ void cp_async16(unsigned smem_addr, const void* g) {
    asm volatile("cp.async.cg.shared.global [%0], [%1], 16;"
                 :: "r"(smem_addr), "l"(g));
}

// ---------------- prep kernels ----------------
// float4 loads + 4 independent partial sums: 16-step chains, 4x MLP
__global__ void cnorm_kernel(const float* __restrict__ centers) {
    int n = blockIdx.x * blockDim.x + threadIdx.x;
    if (n < KCENT) {
        const float4* c = reinterpret_cast<const float4*>(
            centers + (size_t)n * DIMK);
        float s0 = 0.f, s1 = 0.f, s2 = 0.f, s3 = 0.f;
        #pragma unroll
        for (int k = 0; k < DIMK / 4; k++) {
            float4 v = __ldg(c + k);
            s0 = fmaf(v.x, v.x, s0);
            s1 = fmaf(v.y, v.y, s1);
            s2 = fmaf(v.z, v.z, s2);
            s3 = fmaf(v.w, v.w, s3);
        }
        g_cnorm[n] = (s0 + s1) + (s2 + s3);
    }
}

// Build fragment-ordered tf32 hi/lo blob from centers.
__global__ void csplit_kernel(const float* __restrict__ centers) {
    int id = blockIdx.x * blockDim.x + threadIdx.x;   // 128*8*32 = 32768
    if (id >= NTILES * 8 * 32) return;
    int lane = id & 31;
    int q    = (id >> 5) & 7;
    int t    = id >> 8;
    int n = t * 8 + (lane >> 2);
    int k = q * 8 + (lane & 3);
    float x0 = __ldg(centers + (size_t)n * DIMK + k);
    float x1 = __ldg(centers + (size_t)n * DIMK + k + 4);
    unsigned h0, l0, h1, l1;
    split_tf32(x0, h0, l0);
    split_tf32(x1, h1, l1);
    g_bfrag[(t * 8 + q) * 32 + lane] = make_uint4(h0, h1, l0, l1);
}

// ---------------- main: 3xTF32 mma.sync GEMM + fused argmin ----------------
__global__ void __launch_bounds__(THREADS, 2)
label_mma_kernel(const float* __restrict__ inpt, float* __restrict__ out) {
    extern __shared__ __align__(16) unsigned char sm[];
    const unsigned sbase = (unsigned)__cvta_generic_to_shared(sm);
    float* cn_s = reinterpret_cast<float*>(sm + CN_OFF);

    const int tid  = threadIdx.x;
    const int wid  = tid >> 5;
    const int lane = tid & 31;
    const int r    = lane >> 2;   // 0..7
    const int cc   = lane & 3;    // 0..3
    const int m0   = blockIdx.x * BM;
    const int mrow = m0 + wid * 16;

    // Prefetch chunk 0 (linear copy: blob layout == smem layout)
    {
        const unsigned char* src = (const unsigned char*)g_bfrag;
        #pragma unroll
        for (int j = 0; j < CHUNK_BYTES / (THREADS * 16); j++)
            cp_async16(sbase + tid * 16 + j * (THREADS * 16),
                       src + tid * 16 + j * (THREADS * 16));
        asm volatile("cp.async.commit_group;");
    }

    // Center norms -> smem
    for (int i = tid; i < KCENT; i += THREADS) cn_s[i] = g_cnorm[i];

    // A fragments (registers): 8 ksteps x 4 regs, hi+lo
    unsigned ahi[8][4], alo[8][4];
    {
        const float* row0 = inpt + (size_t)(mrow + r) * INROW + DIMK;
        const float* row8 = inpt + (size_t)(mrow + r + 8) * INROW + DIMK;
        #pragma unroll
        for (int q = 0; q < 8; q++) {
            split_tf32(__ldg(row0 + q * 8 + cc),     ahi[q][0], alo[q][0]);
            split_tf32(__ldg(row8 + q * 8 + cc),     ahi[q][1], alo[q][1]);
            split_tf32(__ldg(row0 + q * 8 + cc + 4), ahi[q][2], alo[q][2]);
            split_tf32(__ldg(row8 + q * 8 + cc + 4), ahi[q][3], alo[q][3]);
        }
    }

    // Running first-min per thread: row r (bd0) and row r+8 (bd1)
    float bd0 = __int_as_float(0x7f800000), bd1 = bd0;
    int   bn0 = 0, bn1 = 0;

    #pragma unroll 1
    for (int c = 0; c < NCHUNK; c++) {
        asm volatile("cp.async.wait_group 0;" ::: "memory");
        __syncthreads();   // chunk c visible; all warps done with chunk c-1

        if (c + 1 < NCHUNK) {
            const unsigned char* src =
                (const unsigned char*)g_bfrag + (size_t)(c + 1) * CHUNK_BYTES;
            unsigned dst = sbase + ((c + 1) & 1) * CHUNK_BYTES;
            #pragma unroll
            for (int j = 0; j < CHUNK_BYTES / (THREADS * 16); j++)
                cp_async16(dst + tid * 16 + j * (THREADS * 16),
                           src + tid * 16 + j * (THREADS * 16));
            asm volatile("cp.async.commit_group;");
        }

        const unsigned buf = sbase + (c & 1) * CHUNK_BYTES + lane * 16;

        #pragma unroll
        for (int t8 = 0; t8 < TPC; t8++) {
            // 3 independent accumulators: RAW chain depth 8 instead of 24
            float dhh[4] = {0.f, 0.f, 0.f, 0.f};
            float dhl[4] = {0.f, 0.f, 0.f, 0.f};
            float dlh[4] = {0.f, 0.f, 0.f, 0.f};
            #pragma unroll
            for (int q = 0; q < 8; q++) {
                uint4 b;
                asm volatile("ld.shared.v4.b32 {%0,%1,%2,%3}, [%4];"
                             : "=r"(b.x), "=r"(b.y), "=r"(b.z), "=r"(b.w)
                             : "r"(buf + ((t8 * 8 + q) * 32) * 16));
                mma_tf32(dhh, ahi[q], b.x, b.y);   // hi*hi
                mma_tf32(dhl, ahi[q], b.z, b.w);   // hi*lo
                mma_tf32(dlh, alo[q], b.x, b.y);   // lo*hi
            }
            // epilogue: cols n = base + 2cc, base + 2cc + 1
            const int nbase = c * 64 + t8 * 8 + 2 * cc;
            float2 cn = *reinterpret_cast<const float2*>(cn_s + nbase);
            float d0 = dhh[0] + (dhl[0] + dlh[0]);
            float d1 = dhh[1] + (dhl[1] + dlh[1]);
            float d2 = dhh[2] + (dhl[2] + dlh[2]);
            float d3 = dhh[3] + (dhl[3] + dlh[3]);
            float e0 = fmaf(-2.f, d0, cn.x);   // row r,   col nbase
            float e1 = fmaf(-2.f, d1, cn.y);   // row r,   col nbase+1
            float e2 = fmaf(-2.f, d2, cn.x);   // row r+8, col nbase
            float e3 = fmaf(-2.f, d3, cn.y);   // row r+8, col nbase+1
            // ascending col order + strict < keeps first-min semantics
            if (e0 < bd0) { bd0 = e0; bn0 = nbase; }
            if (e1 < bd0) { bd0 = e1; bn0 = nbase + 1; }
            if (e2 < bd1) { bd1 = e2; bn1 = nbase; }
            if (e3 < bd1) { bd1 = e3; bn1 = nbase + 1; }
        }
    }

    // Reduce across the 4 lanes sharing each row (disjoint n-sets; tie->lower n)
    #pragma unroll
    for (int off = 1; off <= 2; off <<= 1) {
        float od0 = __shfl_xor_sync(0xffffffffu, bd0, off);
        int   on0 = __shfl_xor_sync(0xffffffffu, bn0, off);
        float od1 = __shfl_xor_sync(0xffffffffu, bd1, off);
        int   on1 = __shfl_xor_sync(0xffffffffu, bn1, off);
        if (od0 < bd0 || (od0 == bd0 && on0 < bn0)) { bd0 = od0; bn0 = on0; }
        if (od1 < bd1 || (od1 == bd1 && on1 < bn1)) { bd1 = od1; bn1 = on1; }
    }
    if (cc == 0) {
        out[mrow + r]     = (float)bn0;   // fp32 output dtype
        out[mrow + r + 8] = (float)bn1;
    }
}

extern "C" void kernel_launch(void* const* d_in, const int* in_sizes, int n_in,
                              void* d_out, int out_size) {
    // Identify inputs by element count:
    //   inpt: 16777216 elements (unique); centers1: second 65536-elem tensor
    const float* inpt     = nullptr;
    const float* centers1 = nullptr;
    int centers_seen = 0;
    for (int i = 0; i < n_in; i++) {
        if (in_sizes[i] == NPTS * INROW) {
            inpt = (const float*)d_in[i];
        } else if (in_sizes[i] == KCENT * DIMK) {
            centers_seen++;
            if (centers_seen == 2) centers1 = (const float*)d_in[i];
        }
    }
    if (!inpt)     inpt     = (const float*)d_in[0];
    if (!centers1) centers1 = (const float*)d_in[n_in - 1];

    float* out = (float*)d_out;

    cudaFuncSetAttribute(label_mma_kernel,
                         cudaFuncAttributeMaxDynamicSharedMemorySize, SMEM_REQ);

    cnorm_kernel<<<(KCENT + 255) / 256, 256>>>(centers1);
    csplit_kernel<<<(NTILES * 8 * 32 + 255) / 256, 256>>>(centers1);
    label_mma_kernel<<<NPTS / BM, THREADS, SMEM_REQ>>>(inpt, out);
}